// round 4
// baseline (speedup 1.0000x reference)
#include <cuda_runtime.h>

// Fixed shapes: feat [8,64,512,512] f32, label [8,1,512,512] i32
#define NCLS 19
#define BATCH 8
#define DCH 64
#define HWPX 262144               // 512*512
#define TILE_PX 1024              // 256 threads x 4 px
#define TILES_PER_BATCH 256       // HWPX / TILE_PX
#define BLOCKS_PER_BATCH 37
#define NBLOCKS (BATCH * BLOCKS_PER_BATCH)   // 296 = 2 CTAs/SM on 148 SMs
#define NTHREADS 256
#define MAX_TILES 7               // ceil(256/37)
#define GCH 4                     // channels per pass (float4 bins)
#define EPSF 1e-6f
#define SMEM_BYTES (NCLS * NTHREADS * 16)    // 77824 B of float4 bins

// Persistent scratch (allocation-free rule: device globals; zero at module load,
// re-zeroed by the last CTA of every call -> every call sees zeroed state).
__device__ float g_sums[BATCH][NCLS][DCH];
__device__ float g_counts[BATCH][NCLS];
__device__ unsigned g_done;

__global__ __launch_bounds__(NTHREADS, 2)
void frc_fused_kernel(const float* __restrict__ feat, const int* __restrict__ label,
                      float* __restrict__ out) {
    extern __shared__ float4 bins4[];   // [NCLS * NTHREADS]

    const int tid  = threadIdx.x;
    const int warp = tid >> 5, lane = tid & 31;
    const int b    = blockIdx.x / BLOCKS_PER_BATCH;
    const int r    = blockIdx.x % BLOCKS_PER_BATCH;
    const int t_lo = (r * TILES_PER_BATCH) / BLOCKS_PER_BATCH;
    const int t_hi = ((r + 1) * TILES_PER_BATCH) / BLOCKS_PER_BATCH;
    const int ntiles = t_hi - t_lo;     // 6 or 7

    // ---- Pack this thread's labels (4 px/tile) once; reused for all 64 channels.
    unsigned plab[MAX_TILES];
    {
        const int4* lab4 = (const int4*)(label + (size_t)b * HWPX);
        #pragma unroll
        for (int j = 0; j < MAX_TILES; j++) {
            if (j < ntiles) {
                int4 l = lab4[(t_lo + j) * (TILE_PX / 4) + tid];
                unsigned c0 = (unsigned)l.x; if (c0 >= NCLS) c0 = 0u;   // 255 -> 0
                unsigned c1 = (unsigned)l.y; if (c1 >= NCLS) c1 = 0u;
                unsigned c2 = (unsigned)l.z; if (c2 >= NCLS) c2 = 0u;
                unsigned c3 = (unsigned)l.w; if (c3 >= NCLS) c3 = 0u;
                plab[j] = c0 | (c1 << 8) | (c2 << 16) | (c3 << 24);
            } else {
                plab[j] = 0u;
            }
        }
    }

    // ---- Count pass (onehot.sum): +1.0 per pixel into .x slot.
    #pragma unroll
    for (int c = 0; c < NCLS; c++) bins4[c * NTHREADS + tid] = make_float4(0.f, 0.f, 0.f, 0.f);
    __syncthreads();
    #pragma unroll
    for (int j = 0; j < MAX_TILES; j++) {
        if (j < ntiles) {
            unsigned p = plab[j];
            bins4[(p & 0xFFu) * NTHREADS + tid].x         += 1.0f;
            bins4[((p >> 8) & 0xFFu) * NTHREADS + tid].x  += 1.0f;
            bins4[((p >> 16) & 0xFFu) * NTHREADS + tid].x += 1.0f;
            bins4[(p >> 24) * NTHREADS + tid].x           += 1.0f;
        }
    }
    __syncthreads();
    for (int c = warp; c < NCLS; c += NTHREADS / 32) {
        float s = 0.0f;
        #pragma unroll
        for (int k = 0; k < NTHREADS / 32; k++) s += bins4[c * NTHREADS + lane + k * 32].x;
        for (int off = 16; off; off >>= 1) s += __shfl_down_sync(0xFFFFFFFFu, s, off);
        if (lane == 0) atomicAdd(&g_counts[b][c], s);
    }
    __syncthreads();

    // ---- Channel loop: 4 channels per pass, one float4 RMW per pixel.
    const float4* f4 = (const float4*)(feat + (size_t)b * DCH * HWPX);

    for (int g0 = 0; g0 < DCH; g0 += GCH) {
        #pragma unroll
        for (int c = 0; c < NCLS; c++) bins4[c * NTHREADS + tid] = make_float4(0.f, 0.f, 0.f, 0.f);
        // (own column only -> no sync needed; flush below is fenced by syncthreads)

        float4 buf[2][GCH];
        #pragma unroll
        for (int k = 0; k < GCH; k++)
            buf[0][k] = __ldg(&f4[(size_t)(g0 + k) * (HWPX / 4) + t_lo * (TILE_PX / 4) + tid]);

        #pragma unroll
        for (int j = 0; j < MAX_TILES; j++) {
            if (j + 1 < ntiles) {
                #pragma unroll
                for (int k = 0; k < GCH; k++)
                    buf[(j + 1) & 1][k] =
                        __ldg(&f4[(size_t)(g0 + k) * (HWPX / 4) + (t_lo + j + 1) * (TILE_PX / 4) + tid]);
            }
            if (j < ntiles) {
                unsigned p = plab[j];
                const float4* v = buf[j & 1];
                {   unsigned c = p & 0xFFu;
                    float4* bp = &bins4[c * NTHREADS + tid];
                    float4 t = *bp;
                    t.x += v[0].x; t.y += v[1].x; t.z += v[2].x; t.w += v[3].x; *bp = t; }
                {   unsigned c = (p >> 8) & 0xFFu;
                    float4* bp = &bins4[c * NTHREADS + tid];
                    float4 t = *bp;
                    t.x += v[0].y; t.y += v[1].y; t.z += v[2].y; t.w += v[3].y; *bp = t; }
                {   unsigned c = (p >> 16) & 0xFFu;
                    float4* bp = &bins4[c * NTHREADS + tid];
                    float4 t = *bp;
                    t.x += v[0].z; t.y += v[1].z; t.z += v[2].z; t.w += v[3].z; *bp = t; }
                {   unsigned c = p >> 24;
                    float4* bp = &bins4[c * NTHREADS + tid];
                    float4 t = *bp;
                    t.x += v[0].w; t.y += v[1].w; t.z += v[2].w; t.w += v[3].w; *bp = t; }
            }
        }
        __syncthreads();

        // Flush: warp w handles classes w, w+8, w+16.
        for (int c = warp; c < NCLS; c += NTHREADS / 32) {
            float4 acc = make_float4(0.f, 0.f, 0.f, 0.f);
            #pragma unroll
            for (int k = 0; k < NTHREADS / 32; k++) {
                float4 v = bins4[c * NTHREADS + lane + k * 32];
                acc.x += v.x; acc.y += v.y; acc.z += v.z; acc.w += v.w;
            }
            for (int off = 16; off; off >>= 1) {
                acc.x += __shfl_down_sync(0xFFFFFFFFu, acc.x, off);
                acc.y += __shfl_down_sync(0xFFFFFFFFu, acc.y, off);
                acc.z += __shfl_down_sync(0xFFFFFFFFu, acc.z, off);
                acc.w += __shfl_down_sync(0xFFFFFFFFu, acc.w, off);
            }
            if (lane == 0) {
                atomicAdd(&g_sums[b][c][g0 + 0], acc.x);
                atomicAdd(&g_sums[b][c][g0 + 1], acc.y);
                atomicAdd(&g_sums[b][c][g0 + 2], acc.z);
                atomicAdd(&g_sums[b][c][g0 + 3], acc.w);
            }
        }
        __syncthreads();
    }

    // ---- Fan-in: last CTA to finish runs the epilogue, then re-zeros state.
    __shared__ bool s_last;
    __threadfence();
    __syncthreads();
    if (tid == 0) s_last = (atomicAdd(&g_done, 1u) == NBLOCKS - 1);
    __syncthreads();
    if (!s_last) return;
    __threadfence();

    const int K = NCLS - 1;   // 18
    float* sE    = (float*)bins4;                 // [K][DCH] = 1152 floats
    float* s_num = sE + K * DCH;                  // [NCLS]
    float* s_sq  = s_num + NCLS;                  // [K]
    float* s_cos = s_sq + K;                      // [K*K]
    float* s_dml = s_cos + K * K;                 // [K]

    if (tid < NCLS) {
        float n = 0.0f;
        for (int bb = 0; bb < BATCH; bb++) n += (g_counts[bb][tid] > 0.0f) ? 1.0f : 0.0f;
        s_num[tid] = n;
    }
    __syncthreads();

    // embedding_list[c][d] = sum_b sums/(counts+eps); E = list[1:]/num[1:]
    for (int idx = tid; idx < K * DCH; idx += NTHREADS) {
        int c = idx / DCH + 1;
        int d = idx % DCH;
        float e = 0.0f;
        for (int bb = 0; bb < BATCH; bb++)
            e += g_sums[bb][c][d] / (g_counts[bb][c] + EPSF);
        sE[(c - 1) * DCH + d] = e / s_num[c];
    }
    __syncthreads();

    if (tid < K) {
        float s = 0.0f;
        for (int d = 0; d < DCH; d++) { float x = sE[tid * DCH + d]; s += x * x; }
        s_sq[tid] = s;
    }
    __syncthreads();

    // cos[i][j] = dot(Ei,Ej) / (sq[i]*sq[j])   (faithful: squared norms, no sqrt)
    for (int idx = tid; idx < K * K; idx += NTHREADS) {
        int i = idx / K, j = idx % K;
        float s = 0.0f;
        for (int d = 0; d < DCH; d++) s += sE[i * DCH + d] * sE[j * DCH + d];
        s_cos[idx] = s / (s_sq[i] * s_sq[j]);
    }
    __syncthreads();

    if (tid < K) {
        float m = -1e30f;
        for (int j = 0; j < K; j++) m = fmaxf(m, s_cos[tid * K + j]);
        float s = 0.0f;
        for (int j = 0; j < K; j++) s += expf(s_cos[tid * K + j] - m);
        s_dml[tid] = s_cos[tid * K + tid] - (m + logf(s));
    }
    __syncthreads();

    if (tid == 0) {
        float t = 0.0f;
        for (int i = 0; i < K; i++) t += s_dml[i];
        out[0] = -t / (float)K;
    }

    // Re-zero persistent state for the next call (deterministic per-call behavior).
    __syncthreads();
    for (int i = tid; i < BATCH * NCLS * DCH; i += NTHREADS) (&g_sums[0][0][0])[i] = 0.0f;
    for (int i = tid; i < BATCH * NCLS; i += NTHREADS) (&g_counts[0][0])[i] = 0.0f;
    if (tid == 0) g_done = 0u;
}

// ---------------------------------------------------------------------------
extern "C" void kernel_launch(void* const* d_in, const int* in_sizes, int n_in,
                              void* d_out, int out_size) {
    const float* feat;
    const int* label;
    if (in_sizes[0] == BATCH * DCH * HWPX) {
        feat  = (const float*)d_in[0];
        label = (const int*)d_in[1];
    } else {
        feat  = (const float*)d_in[1];
        label = (const int*)d_in[0];
    }

    // Idempotent attribute set (not a stream op; graph-capture safe).
    cudaFuncSetAttribute(frc_fused_kernel,
                         cudaFuncAttributeMaxDynamicSharedMemorySize, SMEM_BYTES);

    frc_fused_kernel<<<NBLOCKS, NTHREADS, SMEM_BYTES>>>(feat, label, (float*)d_out);
}

// round 9
// speedup vs baseline: 1.0511x; 1.0511x over previous
#include <cuda_runtime.h>

// Fixed shapes: feat [8,64,512,512] f32, label [8,1,512,512] i32
#define NCLS 19
#define BATCH 8
#define DCH 64
#define HWPX 262144               // 512*512
#define TILE_PX 1024              // 256 threads x 4 px
#define TILES_PER_BATCH 256       // HWPX / TILE_PX
#define BLOCKS_PER_BATCH 37
#define NBLOCKS (BATCH * BLOCKS_PER_BATCH)   // 296 = 2 CTAs/SM on 148 SMs
#define NTHREADS 256
#define MAX_TILES 7               // ceil(256/37)
#define GCH 4                     // channels per pass (float4 bins)
#define EPSF 1e-6f
#define SMEM_BYTES (NCLS * NTHREADS * 16)    // 77824 B of float4 bins

// Persistent scratch (allocation-free rule: device globals; zero at module load,
// re-zeroed by the last CTA of every call -> every call sees zeroed state).
__device__ float g_sums[BATCH][NCLS][DCH];
__device__ float g_counts[BATCH][NCLS];
__device__ unsigned g_done;

__global__ __launch_bounds__(NTHREADS, 2)
void frc_fused_kernel(const float* __restrict__ feat, const int* __restrict__ label,
                      float* __restrict__ out) {
    extern __shared__ float4 bins4[];   // [NCLS * NTHREADS]

    const int tid  = threadIdx.x;
    const int warp = tid >> 5, lane = tid & 31;
    const int b    = blockIdx.x / BLOCKS_PER_BATCH;
    const int r    = blockIdx.x % BLOCKS_PER_BATCH;
    const int t_lo = (r * TILES_PER_BATCH) / BLOCKS_PER_BATCH;
    const int t_hi = ((r + 1) * TILES_PER_BATCH) / BLOCKS_PER_BATCH;
    const int ntiles = t_hi - t_lo;     // 6 or 7

    const float4* f4 = (const float4*)(feat + (size_t)b * DCH * HWPX);

#define FPTR(dd, jj) (&f4[(size_t)(dd) * (HWPX / 4) + (t_lo + (jj)) * (TILE_PX / 4) + tid])

    // ---- Pack labels (4 px/tile) once; reused for all 64 channels.
    unsigned plab[MAX_TILES];
    {
        const int4* lab4 = (const int4*)(label + (size_t)b * HWPX);
        #pragma unroll
        for (int j = 0; j < MAX_TILES; j++) {
            if (j < ntiles) {
                int4 l = lab4[(t_lo + j) * (TILE_PX / 4) + tid];
                unsigned c0 = (unsigned)l.x; if (c0 >= NCLS) c0 = 0u;   // 255 -> 0
                unsigned c1 = (unsigned)l.y; if (c1 >= NCLS) c1 = 0u;
                unsigned c2 = (unsigned)l.z; if (c2 >= NCLS) c2 = 0u;
                unsigned c3 = (unsigned)l.w; if (c3 >= NCLS) c3 = 0u;
                plab[j] = c0 | (c1 << 8) | (c2 << 16) | (c3 << 24);
            } else {
                plab[j] = 0u;
            }
        }
    }

    // Triple-buffered tile loads: at tile j we accumulate buf[j%3] while j+2 loads.
    float4 buf[3][GCH];
    #pragma unroll
    for (int k = 0; k < GCH; k++) buf[0][k] = __ldg(FPTR(k, 0));
    #pragma unroll
    for (int k = 0; k < GCH; k++) buf[1][k] = __ldg(FPTR(k, 1));

    // ---- Count pass (onehot.sum): +1.0 per pixel into .x slot (runs under the loads).
    #pragma unroll
    for (int c = 0; c < NCLS; c++) bins4[c * NTHREADS + tid] = make_float4(0.f, 0.f, 0.f, 0.f);
    __syncthreads();
    #pragma unroll
    for (int j = 0; j < MAX_TILES; j++) {
        if (j < ntiles) {
            unsigned p = plab[j];
            bins4[(p & 0xFFu) * NTHREADS + tid].x         += 1.0f;
            bins4[((p >> 8) & 0xFFu) * NTHREADS + tid].x  += 1.0f;
            bins4[((p >> 16) & 0xFFu) * NTHREADS + tid].x += 1.0f;
            bins4[(p >> 24) * NTHREADS + tid].x           += 1.0f;
        }
    }
    __syncthreads();
    for (int c = warp; c < NCLS; c += NTHREADS / 32) {
        float s = 0.0f;
        #pragma unroll
        for (int k = 0; k < NTHREADS / 32; k++) s += bins4[c * NTHREADS + lane + k * 32].x;
        for (int off = 16; off; off >>= 1) s += __shfl_down_sync(0xFFFFFFFFu, s, off);
        if (lane == 0) atomicAdd(&g_counts[b][c], s);
    }
    __syncthreads();

    // ---- Channel loop: 4 channels per pass, one float4 RMW per pixel tap.
    for (int g0 = 0; g0 < DCH; g0 += GCH) {
        // Zero own bin column (thread-private; prior flush completed at loop-tail sync).
        #pragma unroll
        for (int c = 0; c < NCLS; c++) bins4[c * NTHREADS + tid] = make_float4(0.f, 0.f, 0.f, 0.f);

        #pragma unroll
        for (int j = 0; j < MAX_TILES; j++) {
            if (j + 2 < ntiles) {
                #pragma unroll
                for (int k = 0; k < GCH; k++)
                    buf[(j + 2) % 3][k] = __ldg(FPTR(g0 + k, j + 2));
            }
            if (j < ntiles) {
                unsigned p = plab[j];
                const float4* v = buf[j % 3];
                {   unsigned c = p & 0xFFu;
                    float4* bp = &bins4[c * NTHREADS + tid];
                    float4 t = *bp;
                    t.x += v[0].x; t.y += v[1].x; t.z += v[2].x; t.w += v[3].x; *bp = t; }
                {   unsigned c = (p >> 8) & 0xFFu;
                    float4* bp = &bins4[c * NTHREADS + tid];
                    float4 t = *bp;
                    t.x += v[0].y; t.y += v[1].y; t.z += v[2].y; t.w += v[3].y; *bp = t; }
                {   unsigned c = (p >> 16) & 0xFFu;
                    float4* bp = &bins4[c * NTHREADS + tid];
                    float4 t = *bp;
                    t.x += v[0].z; t.y += v[1].z; t.z += v[2].z; t.w += v[3].z; *bp = t; }
                {   unsigned c = p >> 24;
                    float4* bp = &bins4[c * NTHREADS + tid];
                    float4 t = *bp;
                    t.x += v[0].w; t.y += v[1].w; t.z += v[2].w; t.w += v[3].w; *bp = t; }
            }
        }

        // Kick off next group's first two tiles NOW so DRAM stays busy across flush.
        if (g0 + GCH < DCH) {
            #pragma unroll
            for (int k = 0; k < GCH; k++) buf[0][k] = __ldg(FPTR(g0 + GCH + k, 0));
            #pragma unroll
            for (int k = 0; k < GCH; k++) buf[1][k] = __ldg(FPTR(g0 + GCH + k, 1));
        }
        __syncthreads();

        // Flush: warp w handles classes w, w+8, w+16.
        for (int c = warp; c < NCLS; c += NTHREADS / 32) {
            float4 acc = make_float4(0.f, 0.f, 0.f, 0.f);
            #pragma unroll
            for (int k = 0; k < NTHREADS / 32; k++) {
                float4 v = bins4[c * NTHREADS + lane + k * 32];
                acc.x += v.x; acc.y += v.y; acc.z += v.z; acc.w += v.w;
            }
            for (int off = 16; off; off >>= 1) {
                acc.x += __shfl_down_sync(0xFFFFFFFFu, acc.x, off);
                acc.y += __shfl_down_sync(0xFFFFFFFFu, acc.y, off);
                acc.z += __shfl_down_sync(0xFFFFFFFFu, acc.z, off);
                acc.w += __shfl_down_sync(0xFFFFFFFFu, acc.w, off);
            }
            if (lane == 0) {
                atomicAdd(&g_sums[b][c][g0 + 0], acc.x);
                atomicAdd(&g_sums[b][c][g0 + 1], acc.y);
                atomicAdd(&g_sums[b][c][g0 + 2], acc.z);
                atomicAdd(&g_sums[b][c][g0 + 3], acc.w);
            }
        }
        __syncthreads();
    }

    // ---- Fan-in: last CTA runs the epilogue, then re-zeros state.
    __shared__ bool s_last;
    __threadfence();
    __syncthreads();
    if (tid == 0) s_last = (atomicAdd(&g_done, 1u) == NBLOCKS - 1);
    __syncthreads();
    if (!s_last) return;
    __threadfence();

    const int K = NCLS - 1;   // 18
    float* sE    = (float*)bins4;                 // [K][DCH] = 1152 floats
    float* s_num = sE + K * DCH;
    float* s_sq  = s_num + NCLS;
    float* s_cos = s_sq + K;
    float* s_dml = s_cos + K * K;

    if (tid < NCLS) {
        float n = 0.0f;
        for (int bb = 0; bb < BATCH; bb++) n += (g_counts[bb][tid] > 0.0f) ? 1.0f : 0.0f;
        s_num[tid] = n;
    }
    __syncthreads();

    for (int idx = tid; idx < K * DCH; idx += NTHREADS) {
        int c = idx / DCH + 1;
        int d = idx % DCH;
        float e = 0.0f;
        for (int bb = 0; bb < BATCH; bb++)
            e += g_sums[bb][c][d] / (g_counts[bb][c] + EPSF);
        sE[(c - 1) * DCH + d] = e / s_num[c];
    }
    __syncthreads();

    if (tid < K) {
        float s = 0.0f;
        for (int d = 0; d < DCH; d++) { float x = sE[tid * DCH + d]; s += x * x; }
        s_sq[tid] = s;
    }
    __syncthreads();

    for (int idx = tid; idx < K * K; idx += NTHREADS) {
        int i = idx / K, j = idx % K;
        float s = 0.0f;
        for (int d = 0; d < DCH; d++) s += sE[i * DCH + d] * sE[j * DCH + d];
        s_cos[idx] = s / (s_sq[i] * s_sq[j]);
    }
    __syncthreads();

    if (tid < K) {
        float m = -1e30f;
        for (int j = 0; j < K; j++) m = fmaxf(m, s_cos[tid * K + j]);
        float s = 0.0f;
        for (int j = 0; j < K; j++) s += expf(s_cos[tid * K + j] - m);
        s_dml[tid] = s_cos[tid * K + tid] - (m + logf(s));
    }
    __syncthreads();

    if (tid == 0) {
        float t = 0.0f;
        for (int i = 0; i < K; i++) t += s_dml[i];
        out[0] = -t / (float)K;
    }

    // Re-zero persistent state for the next call.
    __syncthreads();
    for (int i = tid; i < BATCH * NCLS * DCH; i += NTHREADS) (&g_sums[0][0][0])[i] = 0.0f;
    for (int i = tid; i < BATCH * NCLS; i += NTHREADS) (&g_counts[0][0])[i] = 0.0f;
    if (tid == 0) g_done = 0u;
}

// ---------------------------------------------------------------------------
extern "C" void kernel_launch(void* const* d_in, const int* in_sizes, int n_in,
                              void* d_out, int out_size) {
    const float* feat;
    const int* label;
    if (in_sizes[0] == BATCH * DCH * HWPX) {
        feat  = (const float*)d_in[0];
        label = (const int*)d_in[1];
    } else {
        feat  = (const float*)d_in[1];
        label = (const int*)d_in[0];
    }

    cudaFuncSetAttribute(frc_fused_kernel,
                         cudaFuncAttributeMaxDynamicSharedMemorySize, SMEM_BYTES);

    frc_fused_kernel<<<NBLOCKS, NTHREADS, SMEM_BYTES>>>(feat, label, (float*)d_out);
}